// round 1
// baseline (speedup 1.0000x reference)
#include <cuda_runtime.h>

// CSR weighted-gather segment sum:
//   out[p, :] = sum_{k in row p} PHI[k] * ctrl_pts[Jm[k], :]
// Rows are defined by inclusive end-offsets num_supp_cumsum (row p spans
// [cum[p-1], cum[p]) with cum[-1] == 0). In this dataset every row has
// exactly 64 entries; we read the cumsum generically but take a vectorized
// fast path when the row length is 64 and the row start is 8B-aligned.
//
// One warp per point:
//  - fast path: lane loads float2 PHI / int2 Jm (coalesced 256B per warp),
//    2 gathers of 12B each from the 6MB (L2-resident) ctrl table, 6 FMAs
//  - butterfly reduce 3 accumulators (15 SHFLs)
//  - lane 0 writes 3 floats

__global__ __launch_bounds__(256)
void thb_eval_kernel(const float* __restrict__ ctrl,
                     const float* __restrict__ phi,
                     const int*   __restrict__ jm,
                     const int*   __restrict__ cum,
                     float*       __restrict__ out,
                     int num_pts)
{
    const int warp = (int)((blockIdx.x * (unsigned)blockDim.x + threadIdx.x) >> 5);
    if (warp >= num_pts) return;
    const int lane = threadIdx.x & 31;

    const int start = (warp == 0) ? 0 : cum[warp - 1];
    const int end   = cum[warp];
    const int n     = end - start;

    float sx = 0.f, sy = 0.f, sz = 0.f;

    if (n == 64 && ((start & 1) == 0)) {
        // 32 lanes * 2 entries = 64 entries, one pass
        const float2* __restrict__ p2 = reinterpret_cast<const float2*>(phi + start);
        const int2*   __restrict__ j2 = reinterpret_cast<const int2*>(jm + start);
        const float2 w = p2[lane];
        const int2   j = j2[lane];

        const float* c0 = ctrl + 3u * (unsigned)j.x;
        const float* c1 = ctrl + 3u * (unsigned)j.y;

        sx = fmaf(w.x, c0[0], sx);
        sy = fmaf(w.x, c0[1], sy);
        sz = fmaf(w.x, c0[2], sz);
        sx = fmaf(w.y, c1[0], sx);
        sy = fmaf(w.y, c1[1], sy);
        sz = fmaf(w.y, c1[2], sz);
    } else {
        for (int k = start + lane; k < end; k += 32) {
            const float w = phi[k];
            const int   j = jm[k];
            const float* c = ctrl + 3u * (unsigned)j;
            sx = fmaf(w, c[0], sx);
            sy = fmaf(w, c[1], sy);
            sz = fmaf(w, c[2], sz);
        }
    }

    #pragma unroll
    for (int off = 16; off > 0; off >>= 1) {
        sx += __shfl_xor_sync(0xFFFFFFFFu, sx, off);
        sy += __shfl_xor_sync(0xFFFFFFFFu, sy, off);
        sz += __shfl_xor_sync(0xFFFFFFFFu, sz, off);
    }

    if (lane == 0) {
        const unsigned o = 3u * (unsigned)warp;
        out[o + 0] = sx;
        out[o + 1] = sy;
        out[o + 2] = sz;
    }
}

extern "C" void kernel_launch(void* const* d_in, const int* in_sizes, int n_in,
                              void* d_out, int out_size)
{
    const float* ctrl = (const float*)d_in[0];   // [N_CTRL, 3] f32
    const float* phi  = (const float*)d_in[1];   // [TOTAL] f32
    const int*   jm   = (const int*)d_in[2];     // [TOTAL] i32
    const int*   cum  = (const int*)d_in[3];     // [P] i32 (inclusive row ends)
    float*       out  = (float*)d_out;           // [P, 3] f32

    const int num_pts = in_sizes[3];

    const int threads = 256;                      // 8 warps -> 8 points per block
    const long long total_threads = (long long)num_pts * 32;
    const int blocks = (int)((total_threads + threads - 1) / threads);

    thb_eval_kernel<<<blocks, threads>>>(ctrl, phi, jm, cum, out, num_pts);
}

// round 2
// speedup vs baseline: 1.2670x; 1.2670x over previous
#include <cuda_runtime.h>

// out[p,:] = sum_{k in row p} PHI[k] * ctrl_pts[Jm[k],:]   (rows = CSR via
// inclusive end-offsets; in this dataset every row is exactly 64 entries).
//
// R1 ncu: L1tex 85.7% (bound), DRAM 17.8%. The 12B gathers (LDG.64+LDG.32,
// lane-scattered) are the wavefront hog. Fix: repack ctrl into a 16B-aligned
// float4 scratch table so each gather is ONE LDG.128 hitting exactly one 32B
// sector (addr = 16j, 16j mod 32 in {0,16}).

#define MAX_CTRL 524288

__device__ __align__(16) float4 g_ctrl4[MAX_CTRL];   // 8 MB static scratch

__global__ __launch_bounds__(256)
void pack_ctrl_kernel(const float* __restrict__ ctrl, int n_ctrl)
{
    int i = blockIdx.x * blockDim.x + threadIdx.x;
    if (i < n_ctrl) {
        const float* c = ctrl + 3u * (unsigned)i;
        g_ctrl4[i] = make_float4(c[0], c[1], c[2], 0.0f);
    }
}

// Fast path: one warp per point, packed float4 gathers.
__global__ __launch_bounds__(256)
void thb_eval_packed_kernel(const float* __restrict__ phi,
                            const int*   __restrict__ jm,
                            const int*   __restrict__ cum,
                            const float* __restrict__ ctrl,   // raw, for odd rows
                            float*       __restrict__ out,
                            int num_pts)
{
    const int warp = (int)((blockIdx.x * (unsigned)blockDim.x + threadIdx.x) >> 5);
    if (warp >= num_pts) return;
    const int lane = threadIdx.x & 31;

    const int start = (warp == 0) ? 0 : cum[warp - 1];
    const int end   = cum[warp];
    const int n     = end - start;

    float sx = 0.f, sy = 0.f, sz = 0.f;

    if (n == 64 && ((start & 1) == 0)) {
        const float2 w = reinterpret_cast<const float2*>(phi + start)[lane];
        const int2   j = reinterpret_cast<const int2*>(jm + start)[lane];

        const float4 c0 = __ldg(&g_ctrl4[j.x]);   // 1 sector each, 1 wavefront
        const float4 c1 = __ldg(&g_ctrl4[j.y]);

        sx = fmaf(w.x, c0.x, fmaf(w.y, c1.x, sx));
        sy = fmaf(w.x, c0.y, fmaf(w.y, c1.y, sy));
        sz = fmaf(w.x, c0.z, fmaf(w.y, c1.z, sz));
    } else {
        for (int k = start + lane; k < end; k += 32) {
            const float w = phi[k];
            const float* c = ctrl + 3u * (unsigned)jm[k];
            sx = fmaf(w, c[0], sx);
            sy = fmaf(w, c[1], sy);
            sz = fmaf(w, c[2], sz);
        }
    }

    #pragma unroll
    for (int off = 16; off > 0; off >>= 1) {
        sx += __shfl_xor_sync(0xFFFFFFFFu, sx, off);
        sy += __shfl_xor_sync(0xFFFFFFFFu, sy, off);
        sz += __shfl_xor_sync(0xFFFFFFFFu, sz, off);
    }

    if (lane == 0) {
        const unsigned o = 3u * (unsigned)warp;
        out[o + 0] = sx;
        out[o + 1] = sy;
        out[o + 2] = sz;
    }
}

// Generic fallback (table too big to pack): same as R1 kernel.
__global__ __launch_bounds__(256)
void thb_eval_raw_kernel(const float* __restrict__ ctrl,
                         const float* __restrict__ phi,
                         const int*   __restrict__ jm,
                         const int*   __restrict__ cum,
                         float*       __restrict__ out,
                         int num_pts)
{
    const int warp = (int)((blockIdx.x * (unsigned)blockDim.x + threadIdx.x) >> 5);
    if (warp >= num_pts) return;
    const int lane = threadIdx.x & 31;

    const int start = (warp == 0) ? 0 : cum[warp - 1];
    const int end   = cum[warp];

    float sx = 0.f, sy = 0.f, sz = 0.f;
    for (int k = start + lane; k < end; k += 32) {
        const float w = phi[k];
        const float* c = ctrl + 3u * (unsigned)jm[k];
        sx = fmaf(w, c[0], sx);
        sy = fmaf(w, c[1], sy);
        sz = fmaf(w, c[2], sz);
    }

    #pragma unroll
    for (int off = 16; off > 0; off >>= 1) {
        sx += __shfl_xor_sync(0xFFFFFFFFu, sx, off);
        sy += __shfl_xor_sync(0xFFFFFFFFu, sy, off);
        sz += __shfl_xor_sync(0xFFFFFFFFu, sz, off);
    }

    if (lane == 0) {
        const unsigned o = 3u * (unsigned)warp;
        out[o + 0] = sx;
        out[o + 1] = sy;
        out[o + 2] = sz;
    }
}

extern "C" void kernel_launch(void* const* d_in, const int* in_sizes, int n_in,
                              void* d_out, int out_size)
{
    const float* ctrl = (const float*)d_in[0];   // [N_CTRL, 3] f32
    const float* phi  = (const float*)d_in[1];   // [TOTAL] f32
    const int*   jm   = (const int*)d_in[2];     // [TOTAL] i32
    const int*   cum  = (const int*)d_in[3];     // [P] i32 inclusive row ends
    float*       out  = (float*)d_out;           // [P, 3] f32

    const int n_ctrl  = in_sizes[0] / 3;
    const int num_pts = in_sizes[3];

    const int threads = 256;
    const long long total_threads = (long long)num_pts * 32;
    const int blocks = (int)((total_threads + threads - 1) / threads);

    if (n_ctrl <= MAX_CTRL) {
        pack_ctrl_kernel<<<(n_ctrl + 255) / 256, 256>>>(ctrl, n_ctrl);
        thb_eval_packed_kernel<<<blocks, threads>>>(phi, jm, cum, ctrl, out, num_pts);
    } else {
        thb_eval_raw_kernel<<<blocks, threads>>>(ctrl, phi, jm, cum, out, num_pts);
    }
}

// round 3
// speedup vs baseline: 1.5808x; 1.2477x over previous
#include <cuda_runtime.h>

// out[p,:] = sum_{k in row p} PHI[k] * ctrl_pts[Jm[k],:]
// R2 ncu: L1=78.7%, DRAM=22.8% — L1tex-wavefront bound (64M random gathers).
// R3: 8 lanes/point, 4 points/warp: MLP=8 gathers per lane, SHFLs cut 6.7x,
// phi/jm loaded as float4/int4 (coalesced). Gather table stays packed float4
// (one 32B sector per gather).

#define MAX_CTRL 524288

__device__ __align__(16) float4 g_ctrl4[MAX_CTRL];   // 8 MB static scratch

__global__ __launch_bounds__(256)
void pack_ctrl_kernel(const float* __restrict__ ctrl, int n_ctrl)
{
    int i = blockIdx.x * blockDim.x + threadIdx.x;
    if (i < n_ctrl) {
        const float* c = ctrl + 3u * (unsigned)i;
        g_ctrl4[i] = make_float4(c[0], c[1], c[2], 0.0f);
    }
}

__global__ __launch_bounds__(256)
void thb_eval_packed_kernel(const float* __restrict__ phi,
                            const int*   __restrict__ jm,
                            const int*   __restrict__ cum,
                            float*       __restrict__ out,
                            int num_pts)
{
    const int tid  = blockIdx.x * blockDim.x + threadIdx.x;
    const int lane = threadIdx.x & 31;
    const int l8   = lane & 7;            // lane within 8-lane group
    const int p    = (tid >> 5) * 4 + (lane >> 3);   // this group's point

    int start = 0, end = 0;
    if (p < num_pts) {
        start = (p == 0) ? 0 : cum[p - 1];
        end   = cum[p];
    }
    const int n = end - start;

    float sx = 0.f, sy = 0.f, sz = 0.f;

    if (n == 64 && ((start & 7) == 0)) {
        // lane covers entries [start + 8*l8, +8): two float4/int4 loads
        const float4* __restrict__ p4 = reinterpret_cast<const float4*>(phi + start);
        const int4*   __restrict__ j4 = reinterpret_cast<const int4*>(jm + start);
        const float4 w0 = __ldcs(&p4[2 * l8 + 0]);
        const float4 w1 = __ldcs(&p4[2 * l8 + 1]);
        const int4   j0 = __ldcs(&j4[2 * l8 + 0]);
        const int4   j1 = __ldcs(&j4[2 * l8 + 1]);

        // 8 independent gathers -> MLP 8
        const float4 c0 = __ldg(&g_ctrl4[j0.x]);
        const float4 c1 = __ldg(&g_ctrl4[j0.y]);
        const float4 c2 = __ldg(&g_ctrl4[j0.z]);
        const float4 c3 = __ldg(&g_ctrl4[j0.w]);
        const float4 c4 = __ldg(&g_ctrl4[j1.x]);
        const float4 c5 = __ldg(&g_ctrl4[j1.y]);
        const float4 c6 = __ldg(&g_ctrl4[j1.z]);
        const float4 c7 = __ldg(&g_ctrl4[j1.w]);

        sx = fmaf(w0.x, c0.x, sx); sy = fmaf(w0.x, c0.y, sy); sz = fmaf(w0.x, c0.z, sz);
        sx = fmaf(w0.y, c1.x, sx); sy = fmaf(w0.y, c1.y, sy); sz = fmaf(w0.y, c1.z, sz);
        sx = fmaf(w0.z, c2.x, sx); sy = fmaf(w0.z, c2.y, sy); sz = fmaf(w0.z, c2.z, sz);
        sx = fmaf(w0.w, c3.x, sx); sy = fmaf(w0.w, c3.y, sy); sz = fmaf(w0.w, c3.z, sz);
        sx = fmaf(w1.x, c4.x, sx); sy = fmaf(w1.x, c4.y, sy); sz = fmaf(w1.x, c4.z, sz);
        sx = fmaf(w1.y, c5.x, sx); sy = fmaf(w1.y, c5.y, sy); sz = fmaf(w1.y, c5.z, sz);
        sx = fmaf(w1.z, c6.x, sx); sy = fmaf(w1.z, c6.y, sy); sz = fmaf(w1.z, c6.z, sz);
        sx = fmaf(w1.w, c7.x, sx); sy = fmaf(w1.w, c7.y, sy); sz = fmaf(w1.w, c7.z, sz);
    } else {
        for (int k = start + l8; k < end; k += 8) {
            const float w  = phi[k];
            const float4 c = __ldg(&g_ctrl4[jm[k]]);
            sx = fmaf(w, c.x, sx);
            sy = fmaf(w, c.y, sy);
            sz = fmaf(w, c.z, sz);
        }
    }

    // reduce within each 8-lane group: 3 butterfly steps x 3 vals = 9 SHFL
    #pragma unroll
    for (int off = 4; off > 0; off >>= 1) {
        sx += __shfl_xor_sync(0xFFFFFFFFu, sx, off);
        sy += __shfl_xor_sync(0xFFFFFFFFu, sy, off);
        sz += __shfl_xor_sync(0xFFFFFFFFu, sz, off);
    }

    if (l8 == 0 && p < num_pts) {
        const unsigned o = 3u * (unsigned)p;
        out[o + 0] = sx;
        out[o + 1] = sy;
        out[o + 2] = sz;
    }
}

// Generic fallback for oversized control tables (no packing possible).
__global__ __launch_bounds__(256)
void thb_eval_raw_kernel(const float* __restrict__ ctrl,
                         const float* __restrict__ phi,
                         const int*   __restrict__ jm,
                         const int*   __restrict__ cum,
                         float*       __restrict__ out,
                         int num_pts)
{
    const int warp = (int)((blockIdx.x * (unsigned)blockDim.x + threadIdx.x) >> 5);
    if (warp >= num_pts) return;
    const int lane = threadIdx.x & 31;

    const int start = (warp == 0) ? 0 : cum[warp - 1];
    const int end   = cum[warp];

    float sx = 0.f, sy = 0.f, sz = 0.f;
    for (int k = start + lane; k < end; k += 32) {
        const float w = phi[k];
        const float* c = ctrl + 3u * (unsigned)jm[k];
        sx = fmaf(w, c[0], sx);
        sy = fmaf(w, c[1], sy);
        sz = fmaf(w, c[2], sz);
    }

    #pragma unroll
    for (int off = 16; off > 0; off >>= 1) {
        sx += __shfl_xor_sync(0xFFFFFFFFu, sx, off);
        sy += __shfl_xor_sync(0xFFFFFFFFu, sy, off);
        sz += __shfl_xor_sync(0xFFFFFFFFu, sz, off);
    }

    if (lane == 0) {
        const unsigned o = 3u * (unsigned)warp;
        out[o + 0] = sx;
        out[o + 1] = sy;
        out[o + 2] = sz;
    }
}

extern "C" void kernel_launch(void* const* d_in, const int* in_sizes, int n_in,
                              void* d_out, int out_size)
{
    const float* ctrl = (const float*)d_in[0];   // [N_CTRL, 3] f32
    const float* phi  = (const float*)d_in[1];   // [TOTAL] f32
    const int*   jm   = (const int*)d_in[2];     // [TOTAL] i32
    const int*   cum  = (const int*)d_in[3];     // [P] i32 inclusive row ends
    float*       out  = (float*)d_out;           // [P, 3] f32

    const int n_ctrl  = in_sizes[0] / 3;
    const int num_pts = in_sizes[3];

    if (n_ctrl <= MAX_CTRL) {
        pack_ctrl_kernel<<<(n_ctrl + 255) / 256, 256>>>(ctrl, n_ctrl);
        // 4 points per warp, 8 warps per block -> 32 points per block
        const int blocks = (num_pts + 31) / 32;
        thb_eval_packed_kernel<<<blocks, 256>>>(phi, jm, cum, out, num_pts);
    } else {
        const int threads = 256;
        const long long total_threads = (long long)num_pts * 32;
        const int blocks = (int)((total_threads + threads - 1) / threads);
        thb_eval_raw_kernel<<<blocks, threads>>>(ctrl, phi, jm, cum, out, num_pts);
    }
}